// round 13
// baseline (speedup 1.0000x reference)
#include <cuda_runtime.h>
#include <cuda_bf16.h>

// ---------------------------------------------------------------------------
// CutsSelector collapsed to scalar-per-node form:
//   v = f2@cls ; u = f1@cls ; p = Wd@v ; q = Ws@v
//   r = we.v ; s = g_b.v ; c0 = f_b.cls + cls_b
//   t[n]=x[n].q ; du[n]=x[n].u ; dp[n]=x[n].p
//   per edge: acc64[rep][dst] += enc(t[src] + r*ea)  (ONE u64 L2 red, exact
//     fixed point: bits 0..51 value-sum, bits 52..63 count; 4 replicas)
//   score = du + c0 + (cnt>0 ? dp + sum_v/cnt + s : 0) ; probs = sigmoid
//
// THREE kernels, PDL-chained (R10-12 validated: 25.1 -> 21.2us):
//   K1 pre_kernel (148 x 1024, ONE grid barrier): block 0 computes the whole
//      setup chain (u,v -> p,q, scalars) while blocks 1-147 issue the 10MB x
//      prologue read + zero acc replicas. One barrier, then the dots.
//   K2 edge_kernel (PDL): prologue loads edge data; gather t + u64 reds.
//   K3 out_kernel  (PDL): decode + sigmoid.
// ---------------------------------------------------------------------------

#define C 128
#define NODE_CAP 24576
#define NREP 4
#define P_NBLK 148
#define P_NTHR 1024
#define NPW    5            /* nodes/warp, blocks 1..147: 147*32*5 = 23520 >= N */
#define E_NTHR 1024
#define O_NTHR 256

#define ENC_OFFSET 4096
#define ENC_SCALE  262144.0f          /* 2^18 */
#define ENC_INV    (1.0f / 262144.0f)
#define CNT_SHIFT  52

__device__ __align__(16) float  g_vec_u[C];
__device__ __align__(16) float  g_vec_p[C];
__device__ __align__(16) float  g_vec_q[C];
__device__ float  g_scalar_r;
__device__ float  g_scalar_s;
__device__ float  g_scalar_c0;
__device__ __align__(16) float  g_t[NODE_CAP];
__device__ __align__(16) float2 g_ddp[NODE_CAP];        // {du, dp}
__device__ __align__(16) unsigned long long g_acc64[NREP * NODE_CAP];
__device__ unsigned g_bar0, g_done0;                    // K1 barrier (self-reset)

__device__ __forceinline__ float warp_sum(float v) {
    #pragma unroll
    for (int o = 16; o > 0; o >>= 1) v += __shfl_xor_sync(0xffffffffu, v, o);
    return v;
}

// Exact fixed-point edge encoding (validated R5-R12, rel_err 1.25e-7).
__device__ __forceinline__ unsigned long long enc_edge(float v) {
    int   vi  = __float2int_rn(v);
    float fr  = v - (float)vi;                   // exact, |fr| <= 0.5
    int   fri = __float2int_rn(fr * ENC_SCALE);  // exact product (2^18)
    return ((unsigned long long)(unsigned)(vi + ENC_OFFSET) << 18)
         + (unsigned long long)(long long)fri
         + (1ULL << CNT_SHIFT);
}

__device__ __forceinline__ void red_u64(unsigned long long* p,
                                        unsigned long long v) {
    asm volatile("red.global.add.u64 [%0], %1;" :: "l"(p), "l"(v) : "memory");
}

__device__ __forceinline__ void spin_barrier(unsigned* bar, unsigned target) {
    __syncthreads();
    if (threadIdx.x == 0) {
        __threadfence();
        atomicAdd(bar, 1u);
        unsigned v;
        do {
            asm volatile("ld.global.acquire.gpu.u32 %0, [%1];"
                         : "=r"(v) : "l"(bar));
        } while (v < target);
    }
    __syncthreads();
}

// ============================ K1: setup (block 0) + t (blocks 1..147) =======
__global__ void __launch_bounds__(P_NTHR, 1)
pre_kernel(const float* __restrict__ x,
           const float* __restrict__ g_w,   // [257,128]
           const float* __restrict__ g_b,   // [128]
           const float* __restrict__ f_w,   // [256,128]
           const float* __restrict__ f_b,   // [128]
           const float* __restrict__ cls_w, // [128]
           const float* __restrict__ cls_b, // [1]
           int N)
{
    const int tid  = threadIdx.x;
    const int bid  = blockIdx.x;
    const int wi   = tid >> 5;
    const int lane = tid & 31;

    __shared__ __align__(16) float scls[C];
    __shared__ __align__(16) float sv[C];

    // Per-warp node assignment (blocks 1..147 only).
    int base = 0, cnt = 0;
    float4 xv[NPW];

    if (bid == 0) {
        // ---- whole setup chain on one block (32 warps, batched loads) ----
        if (tid < C) scls[tid] = __ldg(&cls_w[tid]);
        __syncthreads();
        float4 cc = ((const float4*)scls)[lane];

        float4 a[8];
        // Stage 1: 256 dots f_w rows . cls -> u (0..127) / v (128..255)
        #pragma unroll
        for (int j = 0; j < 8; j++)
            a[j] = __ldg((const float4*)(f_w + (size_t)(wi * 8 + j) * C) + lane);
        #pragma unroll
        for (int j = 0; j < 8; j++) {
            float part = warp_sum(a[j].x * cc.x + a[j].y * cc.y +
                                  a[j].z * cc.z + a[j].w * cc.w);
            if (lane == 0) {
                int d = wi * 8 + j;
                if (d < C) g_vec_u[d] = part;
                else       sv[d - C]  = part;
            }
        }
        __syncthreads();
        float4 vv = ((const float4*)sv)[lane];

        // Stage 2: 256 dots g_w rows . v -> p (0..127) / q (128..255)
        #pragma unroll
        for (int j = 0; j < 8; j++)
            a[j] = __ldg((const float4*)(g_w + (size_t)(wi * 8 + j) * C) + lane);
        #pragma unroll
        for (int j = 0; j < 8; j++) {
            float part = warp_sum(a[j].x * vv.x + a[j].y * vv.y +
                                  a[j].z * vv.z + a[j].w * vv.w);
            if (lane == 0) {
                int d = wi * 8 + j;
                if (d < C) g_vec_p[d]     = part;
                else       g_vec_q[d - C] = part;
            }
        }

        // Scalars (warp 0)
        if (wi == 0) {
            float r = 0.f, s = 0.f, c = 0.f;
            #pragma unroll
            for (int k = lane; k < C; k += 32) {
                float vk = sv[k];
                r += __ldg(&g_w[2 * C * C + k]) * vk;
                s += __ldg(&g_b[k]) * vk;
                c += __ldg(&f_b[k]) * scls[k];
            }
            r = warp_sum(r); s = warp_sum(s); c = warp_sum(c);
            if (lane == 0) {
                g_scalar_r  = r;
                g_scalar_s  = s;
                g_scalar_c0 = c + __ldg(&cls_b[0]);
            }
        }
    } else {
        // ---- prologue: issue this warp's x rows (consumed after barrier) ----
        const int gw = (bid - 1) * (P_NTHR / 32) + wi;   // 0..4703
        base = gw * NPW;
        cnt  = (base < N) ? ((N - base < NPW) ? (N - base) : NPW) : 0;
        #pragma unroll
        for (int j = 0; j < NPW; j++)
            if (j < cnt)
                xv[j] = __ldg((const float4*)(x + (size_t)(base + j) * C) + lane);

        // ---- zero accumulator replicas (147*1024 = 150528 >= 98304) ----
        int i = (bid - 1) * P_NTHR + tid;
        if (i < NREP * NODE_CAP) g_acc64[i] = 0ULL;
    }

    // ---- single grid barrier: setup published, x loads in flight ----
    spin_barrier(&g_bar0, (unsigned)P_NBLK);

    // ---- dots (blocks 1..147): q/u/p are L2-hot after barrier ----
    if (cnt > 0) {
        float4 qv = *((const float4*)g_vec_q + lane);
        float4 uv = *((const float4*)g_vec_u + lane);
        float4 pv = *((const float4*)g_vec_p + lane);
        #pragma unroll
        for (int j = 0; j < NPW; j++) {
            if (j < cnt) {
                float dq = xv[j].x * qv.x + xv[j].y * qv.y +
                           xv[j].z * qv.z + xv[j].w * qv.w;
                float du = xv[j].x * uv.x + xv[j].y * uv.y +
                           xv[j].z * uv.z + xv[j].w * uv.w;
                float dp = xv[j].x * pv.x + xv[j].y * pv.y +
                           xv[j].z * pv.z + xv[j].w * pv.w;
                #pragma unroll
                for (int o = 16; o > 0; o >>= 1) {
                    dq += __shfl_xor_sync(0xffffffffu, dq, o);
                    du += __shfl_xor_sync(0xffffffffu, du, o);
                    dp += __shfl_xor_sync(0xffffffffu, dp, o);
                }
                if (lane == 0) {
                    g_t[base + j]   = dq;
                    g_ddp[base + j] = make_float2(du, dp);
                }
            }
        }
    }

    cudaTriggerProgrammaticLaunchCompletion();

    // ---- self-reset barrier counters for graph replay ----
    __syncthreads();
    if (tid == 0) {
        __threadfence();
        unsigned old = atomicAdd(&g_done0, 1u);
        if (old == (unsigned)P_NBLK - 1u) {
            g_bar0 = 0u; g_done0 = 0u;
            __threadfence();
        }
    }
}

// ============================ K2: edges (PDL) ===============================
// 2 edges per thread. Prologue: load edge indices/attrs, sync, then gather
// t + one u64 red per edge.
__global__ void __launch_bounds__(E_NTHR, 1)
edge_kernel(const void*  __restrict__ eidx,
            const float* __restrict__ ea,
            long long E)
{
    const int tid  = threadIdx.x;
    const long long gtid  = (long long)blockIdx.x * E_NTHR + tid;
    const long long pairs = E >> 1;

    // per-warp dtype sniff: int64 nonneg < 2^31 shows zeros at odd int32 slots
    const int lane = tid & 31;
    int is64;
    {
        const int* p = (const int*)eidx;
        int ok = (p[2 * lane + 1] == 0) &&
                 (p[2 * (lane + 32) + 1] == 0) &&
                 (p[2 * (lane + 64) + 1] == 0);
        unsigned b = __ballot_sync(0xffffffffu, ok);
        is64 = (b == 0xffffffffu) ? 1 : 0;
    }

    long long s0 = 0, s1 = 0, d0 = 0, d1 = 0;
    float2 e2 = make_float2(0.f, 0.f);
    const bool active = (gtid < pairs);
    if (active) {
        e2 = __ldg((const float2*)ea + gtid);
        if (is64) {
            const longlong2* ps = (const longlong2*)eidx;
            const longlong2* pd = (const longlong2*)((const long long*)eidx + E);
            longlong2 a = ps[gtid];
            longlong2 c = pd[gtid];
            s0 = a.x; s1 = a.y; d0 = c.x; d1 = c.y;
        } else {
            const int2* ps = (const int2*)eidx;
            const int2* pd = (const int2*)((const int*)eidx + E);
            int2 a = ps[gtid];
            int2 c = pd[gtid];
            s0 = a.x; s1 = a.y; d0 = c.x; d1 = c.y;
        }
    }

    cudaGridDependencySynchronize();   // g_t / g_scalar_r / zeroed acc visible

    const float rs = g_scalar_r;
    unsigned long long* acc =
        g_acc64 + (size_t)(blockIdx.x & (NREP - 1)) * NODE_CAP;

    if (active) {
        float v0 = __ldg(&g_t[s0]) + e2.x * rs;
        float v1 = __ldg(&g_t[s1]) + e2.y * rs;
        red_u64(&acc[d0], enc_edge(v0));
        red_u64(&acc[d1], enc_edge(v1));
    }
    if (gtid == 0 && (E & 1)) {
        if (is64) {
            const long long* p = (const long long*)eidx;
            float v = __ldg(&g_t[p[E - 1]]) + ea[E - 1] * rs;
            red_u64(&acc[p[2 * E - 1]], enc_edge(v));
        } else {
            const int* p = (const int*)eidx;
            float v = __ldg(&g_t[p[E - 1]]) + ea[E - 1] * rs;
            red_u64(&acc[p[2 * E - 1]], enc_edge(v));
        }
    }
    // Implicit PDL trigger at exit: out kernel must see ALL reds.
}

// ============================ K3: output (PDL) ==============================
__global__ void __launch_bounds__(O_NTHR, 8)
out_kernel(float* __restrict__ out, int N, int twopart)
{
    const int n = blockIdx.x * O_NTHR + threadIdx.x;

    float2 ddp = make_float2(0.f, 0.f);
    if (n < N) ddp = g_ddp[n];

    cudaGridDependencySynchronize();   // all edge reds complete

    if (n >= N) return;

    unsigned long long acc = g_acc64[n]
                           + g_acc64[NODE_CAP + n]
                           + g_acc64[2 * NODE_CAP + n]
                           + g_acc64[3 * NODE_CAP + n];
    unsigned cnt = (unsigned)(acc >> CNT_SHIFT);
    unsigned long long raw = acc & ((1ULL << CNT_SHIFT) - 1ULL);
    float score = ddp.x + g_scalar_c0;
    if (cnt > 0u) {
        // hi, lo and 4096*cnt are exact integers < 2^24 in fp32.
        float hi = (float)(long long)(raw >> 18);
        float lo = (float)(int)(raw & 0x3FFFFULL);
        float sum_v = (hi - (float)ENC_OFFSET * (float)cnt) + lo * ENC_INV;
        score += ddp.y + sum_v / (float)cnt + g_scalar_s;
    }
    float pr = 1.0f / (1.0f + __expf(-score));
    if (twopart) {
        out[n]     = (pr > 0.5f) ? 1.0f : 0.0f;
        out[N + n] = pr;
    } else {
        out[n] = pr;
    }
}

// ============================ host ==========================================
static void launch_pdl(const void* func, dim3 grid, dim3 block, void** args) {
    cudaLaunchConfig_t cfg = {};
    cfg.gridDim  = grid;
    cfg.blockDim = block;
    cfg.dynamicSmemBytes = 0;
    cfg.stream = 0;
    cudaLaunchAttribute attr[1];
    attr[0].id = cudaLaunchAttributeProgrammaticStreamSerialization;
    attr[0].val.programmaticStreamSerializationAllowed = 1;
    cfg.attrs = attr;
    cfg.numAttrs = 1;
    cudaLaunchKernelExC(&cfg, func, args);
}

extern "C" void kernel_launch(void* const* d_in, const int* in_sizes, int n_in,
                              void* d_out, int out_size) {
    // metadata order: x_a, edge_index, edge_attr, g_w, g_b, f_w, f_b, cls_w, cls_b
    const float* x_a        = (const float*)d_in[0];
    const void*  edge_index =               d_in[1];
    const float* edge_attr  = (const float*)d_in[2];
    const float* g_w        = (const float*)d_in[3];
    const float* g_b        = (const float*)d_in[4];
    const float* f_w        = (const float*)d_in[5];
    const float* f_b        = (const float*)d_in[6];
    const float* cls_w      = (const float*)d_in[7];
    const float* cls_b      = (const float*)d_in[8];
    float* out = (float*)d_out;

    int       N = in_sizes[0] / C;        // 20000
    long long E = (long long)in_sizes[2]; // 640000
    int twopart = (out_size >= 2 * N) ? 1 : 0;

    pre_kernel<<<P_NBLK, P_NTHR>>>(x_a, g_w, g_b, f_w, f_b, cls_w, cls_b, N);

    {   // edge kernel: 2 edges/thread
        long long pairs = E >> 1;
        dim3 grid((unsigned)((pairs + E_NTHR - 1) / E_NTHR));
        void* args[] = {(void*)&edge_index, (void*)&edge_attr, (void*)&E};
        launch_pdl((const void*)edge_kernel, grid, dim3(E_NTHR), args);
    }
    {   // out kernel
        dim3 grid((N + O_NTHR - 1) / O_NTHR);
        void* args[] = {(void*)&out, (void*)&N, (void*)&twopart};
        launch_pdl((const void*)out_kernel, grid, dim3(O_NTHR), args);
    }
}

// round 14
// speedup vs baseline: 1.1094x; 1.1094x over previous
#include <cuda_runtime.h>
#include <cuda_bf16.h>

// ---------------------------------------------------------------------------
// CutsSelector collapsed to scalar-per-node form:
//   v = f2@cls ; u = f1@cls ; p = Wd@v ; q = Ws@v
//   r = we.v ; s = g_b.v ; c0 = f_b.cls + cls_b
//   t[n]=x[n].q ; du[n]=x[n].u ; dp[n]=x[n].p
//   per edge: acc64[rep][dst] += enc(t[src] + r*ea)  (ONE u64 L2 red, exact
//     fixed point: bits 0..51 value-sum, bits 52..63 count; 4 replicas)
//   score = du + c0 + (cnt>0 ? dp + sum_v/cnt + s : 0) ; probs = sigmoid
//
// THREE kernels, PDL-chained. K1 has NO full-grid barrier:
//   blocks 0..7: distributed matvec stage1 -> flag c1 -> stage2 -> flag c2
//   block  8   : scalars after c1 -> flag c2
//   blocks 9..147: x prologue loads + zero acc, spin on c2 only, then dots.
// Nobody waits on the slowest of 148 blocks (R12/R13 barrier regressions).
// ---------------------------------------------------------------------------

#define C 128
#define NODE_CAP 24576
#define NREP 4
#define P_NBLK 148
#define P_NTHR 1024
#define SB     9            /* setup blocks: 0..7 matvec, 8 scalars */
#define NPW    5            /* nodes/warp, blocks 9..147: 139*32*5 = 22240 >= N */
#define E_NTHR 1024
#define O_NTHR 256

#define ENC_OFFSET 4096
#define ENC_SCALE  262144.0f          /* 2^18 */
#define ENC_INV    (1.0f / 262144.0f)
#define CNT_SHIFT  52

__device__ __align__(16) float  g_vec_u[C];
__device__ __align__(16) float  g_vec_v[C];
__device__ __align__(16) float  g_vec_p[C];
__device__ __align__(16) float  g_vec_q[C];
__device__ float  g_scalar_r;
__device__ float  g_scalar_s;
__device__ float  g_scalar_c0;
__device__ __align__(16) float  g_t[NODE_CAP];
__device__ __align__(16) float2 g_ddp[NODE_CAP];        // {du, dp}
__device__ __align__(16) unsigned long long g_acc64[NREP * NODE_CAP];
__device__ unsigned g_c1, g_c2, g_doneP;                // K1 flags (self-reset)

__device__ __forceinline__ float warp_sum(float v) {
    #pragma unroll
    for (int o = 16; o > 0; o >>= 1) v += __shfl_xor_sync(0xffffffffu, v, o);
    return v;
}

// Exact fixed-point edge encoding (validated R5-R13, rel_err 1.25e-7).
__device__ __forceinline__ unsigned long long enc_edge(float v) {
    int   vi  = __float2int_rn(v);
    float fr  = v - (float)vi;                   // exact, |fr| <= 0.5
    int   fri = __float2int_rn(fr * ENC_SCALE);  // exact product (2^18)
    return ((unsigned long long)(unsigned)(vi + ENC_OFFSET) << 18)
         + (unsigned long long)(long long)fri
         + (1ULL << CNT_SHIFT);
}

__device__ __forceinline__ void red_u64(unsigned long long* p,
                                        unsigned long long v) {
    asm volatile("red.global.add.u64 [%0], %1;" :: "l"(p), "l"(v) : "memory");
}

__device__ __forceinline__ void flag_bump(unsigned* c) {
    __threadfence();
    atomicAdd(c, 1u);
}

__device__ __forceinline__ void flag_wait(unsigned* c, unsigned target) {
    if (threadIdx.x == 0) {
        unsigned v;
        do {
            asm volatile("ld.global.acquire.gpu.u32 %0, [%1];"
                         : "=r"(v) : "l"(c));
        } while (v < target);
    }
    __syncthreads();
}

// ============================ K1: setup flags + t ===========================
__global__ void __launch_bounds__(P_NTHR, 1)
pre_kernel(const float* __restrict__ x,
           const float* __restrict__ g_w,   // [257,128]
           const float* __restrict__ g_b,   // [128]
           const float* __restrict__ f_w,   // [256,128]
           const float* __restrict__ f_b,   // [128]
           const float* __restrict__ cls_w, // [128]
           const float* __restrict__ cls_b, // [1]
           int N)
{
    const int tid  = threadIdx.x;
    const int bid  = blockIdx.x;
    const int wi   = tid >> 5;
    const int lane = tid & 31;

    if (bid < 8) {
        // ---- stage 1: one f_w row per warp (gwarp = bid*32+wi, 0..255) ----
        const int gwarp = bid * 32 + wi;
        {
            float4 cc = __ldg((const float4*)cls_w + lane);
            float4 a  = __ldg((const float4*)(f_w + (size_t)gwarp * C) + lane);
            float part = warp_sum(a.x * cc.x + a.y * cc.y +
                                  a.z * cc.z + a.w * cc.w);
            if (lane == 0) {
                if (gwarp < C) g_vec_u[gwarp] = part;
                else           g_vec_v[gwarp - C] = part;
            }
        }
        __syncthreads();
        if (tid == 0) flag_bump(&g_c1);
        flag_wait(&g_c1, 8u);

        // ---- stage 2: one g_w row per warp ----
        {
            float4 vv = *((const float4*)g_vec_v + lane);  // L2-hot
            float4 a  = __ldg((const float4*)(g_w + (size_t)gwarp * C) + lane);
            float part = warp_sum(a.x * vv.x + a.y * vv.y +
                                  a.z * vv.z + a.w * vv.w);
            if (lane == 0) {
                if (gwarp < C) g_vec_p[gwarp]     = part;
                else           g_vec_q[gwarp - C] = part;
            }
        }
        __syncthreads();
        if (tid == 0) flag_bump(&g_c2);
    } else if (bid == 8) {
        // ---- scalars: wait for v, then r/s/c0 ----
        flag_wait(&g_c1, 8u);
        if (wi == 0) {
            float r = 0.f, s = 0.f, c = 0.f;
            #pragma unroll
            for (int k = lane; k < C; k += 32) {
                float vk = g_vec_v[k];
                r += __ldg(&g_w[2 * C * C + k]) * vk;
                s += __ldg(&g_b[k]) * vk;
                c += __ldg(&f_b[k]) * __ldg(&cls_w[k]);
            }
            r = warp_sum(r); s = warp_sum(s); c = warp_sum(c);
            if (lane == 0) {
                g_scalar_r  = r;
                g_scalar_s  = s;
                g_scalar_c0 = c + __ldg(&cls_b[0]);
            }
        }
        __syncthreads();
        if (tid == 0) flag_bump(&g_c2);
    } else {
        // ---- data blocks 9..147: prologue x loads + zero acc ----
        const int gw   = (bid - SB) * (P_NTHR / 32) + wi;   // 0..4447
        const int base = gw * NPW;
        const int cnt  = (base < N) ? ((N - base < NPW) ? (N - base) : NPW) : 0;
        float4 xv[NPW];
        #pragma unroll
        for (int j = 0; j < NPW; j++)
            if (j < cnt)
                xv[j] = __ldg((const float4*)(x + (size_t)(base + j) * C) + lane);

        {   // zero acc replicas: 139*1024 = 142336 >= 98304
            int i = (bid - SB) * P_NTHR + tid;
            if (i < NREP * NODE_CAP) g_acc64[i] = 0ULL;
        }

        // ---- wait only for setup completion (not for other data blocks) ----
        flag_wait(&g_c2, (unsigned)SB);

        if (cnt > 0) {
            float4 qv = *((const float4*)g_vec_q + lane);
            float4 uv = *((const float4*)g_vec_u + lane);
            float4 pv = *((const float4*)g_vec_p + lane);
            #pragma unroll
            for (int j = 0; j < NPW; j++) {
                if (j < cnt) {
                    float dq = xv[j].x * qv.x + xv[j].y * qv.y +
                               xv[j].z * qv.z + xv[j].w * qv.w;
                    float du = xv[j].x * uv.x + xv[j].y * uv.y +
                               xv[j].z * uv.z + xv[j].w * uv.w;
                    float dp = xv[j].x * pv.x + xv[j].y * pv.y +
                               xv[j].z * pv.z + xv[j].w * pv.w;
                    #pragma unroll
                    for (int o = 16; o > 0; o >>= 1) {
                        dq += __shfl_xor_sync(0xffffffffu, dq, o);
                        du += __shfl_xor_sync(0xffffffffu, du, o);
                        dp += __shfl_xor_sync(0xffffffffu, dp, o);
                    }
                    if (lane == 0) {
                        g_t[base + j]   = dq;
                        g_ddp[base + j] = make_float2(du, dp);
                    }
                }
            }
        }
    }

    cudaTriggerProgrammaticLaunchCompletion();

    // ---- completion count; last block resets flags for graph replay ----
    __syncthreads();
    if (tid == 0) {
        __threadfence();
        unsigned old = atomicAdd(&g_doneP, 1u);
        if (old == (unsigned)P_NBLK - 1u) {
            g_c1 = 0u; g_c2 = 0u; g_doneP = 0u;
            __threadfence();
        }
    }
}

// ============================ K2: edges (PDL) ===============================
// 2 edges per thread. Prologue: load edge indices/attrs, sync, then gather
// t + one u64 red per edge.
__global__ void __launch_bounds__(E_NTHR, 1)
edge_kernel(const void*  __restrict__ eidx,
            const float* __restrict__ ea,
            long long E)
{
    const int tid  = threadIdx.x;
    const long long gtid  = (long long)blockIdx.x * E_NTHR + tid;
    const long long pairs = E >> 1;

    // per-warp dtype sniff: int64 nonneg < 2^31 shows zeros at odd int32 slots
    const int lane = tid & 31;
    int is64;
    {
        const int* p = (const int*)eidx;
        int ok = (p[2 * lane + 1] == 0) &&
                 (p[2 * (lane + 32) + 1] == 0) &&
                 (p[2 * (lane + 64) + 1] == 0);
        unsigned b = __ballot_sync(0xffffffffu, ok);
        is64 = (b == 0xffffffffu) ? 1 : 0;
    }

    long long s0 = 0, s1 = 0, d0 = 0, d1 = 0;
    float2 e2 = make_float2(0.f, 0.f);
    const bool active = (gtid < pairs);
    if (active) {
        e2 = __ldg((const float2*)ea + gtid);
        if (is64) {
            const longlong2* ps = (const longlong2*)eidx;
            const longlong2* pd = (const longlong2*)((const long long*)eidx + E);
            longlong2 a = ps[gtid];
            longlong2 c = pd[gtid];
            s0 = a.x; s1 = a.y; d0 = c.x; d1 = c.y;
        } else {
            const int2* ps = (const int2*)eidx;
            const int2* pd = (const int2*)((const int*)eidx + E);
            int2 a = ps[gtid];
            int2 c = pd[gtid];
            s0 = a.x; s1 = a.y; d0 = c.x; d1 = c.y;
        }
    }

    cudaGridDependencySynchronize();   // g_t / g_scalar_r / zeroed acc visible

    const float rs = g_scalar_r;
    unsigned long long* acc =
        g_acc64 + (size_t)(blockIdx.x & (NREP - 1)) * NODE_CAP;

    if (active) {
        float v0 = __ldg(&g_t[s0]) + e2.x * rs;
        float v1 = __ldg(&g_t[s1]) + e2.y * rs;
        red_u64(&acc[d0], enc_edge(v0));
        red_u64(&acc[d1], enc_edge(v1));
    }
    if (gtid == 0 && (E & 1)) {
        if (is64) {
            const long long* p = (const long long*)eidx;
            float v = __ldg(&g_t[p[E - 1]]) + ea[E - 1] * rs;
            red_u64(&acc[p[2 * E - 1]], enc_edge(v));
        } else {
            const int* p = (const int*)eidx;
            float v = __ldg(&g_t[p[E - 1]]) + ea[E - 1] * rs;
            red_u64(&acc[p[2 * E - 1]], enc_edge(v));
        }
    }
    // Implicit PDL trigger at exit: out kernel must see ALL reds.
}

// ============================ K3: output (PDL) ==============================
__global__ void __launch_bounds__(O_NTHR, 8)
out_kernel(float* __restrict__ out, int N, int twopart)
{
    const int n = blockIdx.x * O_NTHR + threadIdx.x;

    float2 ddp = make_float2(0.f, 0.f);
    if (n < N) ddp = g_ddp[n];

    cudaGridDependencySynchronize();   // all edge reds complete

    if (n >= N) return;

    unsigned long long acc = g_acc64[n]
                           + g_acc64[NODE_CAP + n]
                           + g_acc64[2 * NODE_CAP + n]
                           + g_acc64[3 * NODE_CAP + n];
    unsigned cnt = (unsigned)(acc >> CNT_SHIFT);
    unsigned long long raw = acc & ((1ULL << CNT_SHIFT) - 1ULL);
    float score = ddp.x + g_scalar_c0;
    if (cnt > 0u) {
        // hi, lo and 4096*cnt are exact integers < 2^24 in fp32.
        float hi = (float)(long long)(raw >> 18);
        float lo = (float)(int)(raw & 0x3FFFFULL);
        float sum_v = (hi - (float)ENC_OFFSET * (float)cnt) + lo * ENC_INV;
        score += ddp.y + sum_v / (float)cnt + g_scalar_s;
    }
    float pr = 1.0f / (1.0f + __expf(-score));
    if (twopart) {
        out[n]     = (pr > 0.5f) ? 1.0f : 0.0f;
        out[N + n] = pr;
    } else {
        out[n] = pr;
    }
}

// ============================ host ==========================================
static void launch_pdl(const void* func, dim3 grid, dim3 block, void** args) {
    cudaLaunchConfig_t cfg = {};
    cfg.gridDim  = grid;
    cfg.blockDim = block;
    cfg.dynamicSmemBytes = 0;
    cfg.stream = 0;
    cudaLaunchAttribute attr[1];
    attr[0].id = cudaLaunchAttributeProgrammaticStreamSerialization;
    attr[0].val.programmaticStreamSerializationAllowed = 1;
    cfg.attrs = attr;
    cfg.numAttrs = 1;
    cudaLaunchKernelExC(&cfg, func, args);
}

extern "C" void kernel_launch(void* const* d_in, const int* in_sizes, int n_in,
                              void* d_out, int out_size) {
    // metadata order: x_a, edge_index, edge_attr, g_w, g_b, f_w, f_b, cls_w, cls_b
    const float* x_a        = (const float*)d_in[0];
    const void*  edge_index =               d_in[1];
    const float* edge_attr  = (const float*)d_in[2];
    const float* g_w        = (const float*)d_in[3];
    const float* g_b        = (const float*)d_in[4];
    const float* f_w        = (const float*)d_in[5];
    const float* f_b        = (const float*)d_in[6];
    const float* cls_w      = (const float*)d_in[7];
    const float* cls_b      = (const float*)d_in[8];
    float* out = (float*)d_out;

    int       N = in_sizes[0] / C;        // 20000
    long long E = (long long)in_sizes[2]; // 640000
    int twopart = (out_size >= 2 * N) ? 1 : 0;

    pre_kernel<<<P_NBLK, P_NTHR>>>(x_a, g_w, g_b, f_w, f_b, cls_w, cls_b, N);

    {   // edge kernel: 2 edges/thread
        long long pairs = E >> 1;
        dim3 grid((unsigned)((pairs + E_NTHR - 1) / E_NTHR));
        void* args[] = {(void*)&edge_index, (void*)&edge_attr, (void*)&E};
        launch_pdl((const void*)edge_kernel, grid, dim3(E_NTHR), args);
    }
    {   // out kernel
        dim3 grid((N + O_NTHR - 1) / O_NTHR);
        void* args[] = {(void*)&out, (void*)&N, (void*)&twopart};
        launch_pdl((const void*)out_kernel, grid, dim3(O_NTHR), args);
    }
}

// round 15
// speedup vs baseline: 1.2000x; 1.0817x over previous
#include <cuda_runtime.h>
#include <cuda_bf16.h>

// ---------------------------------------------------------------------------
// CutsSelector collapsed to scalar-per-node form:
//   v = f2@cls ; u = f1@cls ; p = Wd@v ; q = Ws@v
//   r = we.v ; s = g_b.v ; c0 = f_b.cls + cls_b
//   t[n]=x[n].q ; du[n]=x[n].u ; dp[n]=x[n].p
//   per edge: acc64[rep][dst] += enc(t[src] + r*ea)  (ONE u64 L2 red, exact
//     fixed point: bits 0..51 value-sum, bits 52..63 count; 4 replicas)
//   score = du + c0 + (cnt>0 ? dp + sum_v/cnt + s : 0) ; probs = sigmoid
//
// THREE kernels, PDL-chained (best R14: 20.8us):
//   K1 pre_kernel: flag-based setup (blocks 0..8) || x prologue + dots
//      (blocks 9..147) — no full-grid barrier (R14 validated).
//   K2 edge_kernel (148 x 1024, 80KB smem): prologue loads edge pairs during
//      K1; after sync, stages g_t into SMEM (LDS gathers, ~4cyc vs ~32
//      L1tex wavefronts) + one u64 red per edge.
//   K3 out_kernel (PDL): decode + sigmoid.
// ---------------------------------------------------------------------------

#define C 128
#define NODE_CAP 24576
#define NREP 4
#define P_NBLK 148
#define P_NTHR 1024
#define SB     9
#define NPW    5            /* nodes/warp, blocks 9..147: 139*32*5 = 22240 >= N */
#define E_NBLK 148
#define E_NTHR 1024
#define O_NTHR 256

#define ENC_OFFSET 4096
#define ENC_SCALE  262144.0f          /* 2^18 */
#define ENC_INV    (1.0f / 262144.0f)
#define CNT_SHIFT  52

__device__ __align__(16) float  g_vec_u[C];
__device__ __align__(16) float  g_vec_v[C];
__device__ __align__(16) float  g_vec_p[C];
__device__ __align__(16) float  g_vec_q[C];
__device__ float  g_scalar_r;
__device__ float  g_scalar_s;
__device__ float  g_scalar_c0;
__device__ __align__(16) float  g_t[NODE_CAP];
__device__ __align__(16) float2 g_ddp[NODE_CAP];        // {du, dp}
__device__ __align__(16) unsigned long long g_acc64[NREP * NODE_CAP];
__device__ unsigned g_c1, g_c2, g_doneP;                // K1 flags (self-reset)

__device__ __forceinline__ float warp_sum(float v) {
    #pragma unroll
    for (int o = 16; o > 0; o >>= 1) v += __shfl_xor_sync(0xffffffffu, v, o);
    return v;
}

// Exact fixed-point edge encoding (validated R5-R14, rel_err 1.25e-7).
__device__ __forceinline__ unsigned long long enc_edge(float v) {
    int   vi  = __float2int_rn(v);
    float fr  = v - (float)vi;                   // exact, |fr| <= 0.5
    int   fri = __float2int_rn(fr * ENC_SCALE);  // exact product (2^18)
    return ((unsigned long long)(unsigned)(vi + ENC_OFFSET) << 18)
         + (unsigned long long)(long long)fri
         + (1ULL << CNT_SHIFT);
}

__device__ __forceinline__ void red_u64(unsigned long long* p,
                                        unsigned long long v) {
    asm volatile("red.global.add.u64 [%0], %1;" :: "l"(p), "l"(v) : "memory");
}

__device__ __forceinline__ void flag_bump(unsigned* c) {
    __threadfence();
    atomicAdd(c, 1u);
}

__device__ __forceinline__ void flag_wait(unsigned* c, unsigned target) {
    if (threadIdx.x == 0) {
        unsigned v;
        do {
            asm volatile("ld.global.acquire.gpu.u32 %0, [%1];"
                         : "=r"(v) : "l"(c));
        } while (v < target);
    }
    __syncthreads();
}

// ============================ K1: setup flags + t (R14 validated) ===========
__global__ void __launch_bounds__(P_NTHR, 1)
pre_kernel(const float* __restrict__ x,
           const float* __restrict__ g_w,   // [257,128]
           const float* __restrict__ g_b,   // [128]
           const float* __restrict__ f_w,   // [256,128]
           const float* __restrict__ f_b,   // [128]
           const float* __restrict__ cls_w, // [128]
           const float* __restrict__ cls_b, // [1]
           int N)
{
    const int tid  = threadIdx.x;
    const int bid  = blockIdx.x;
    const int wi   = tid >> 5;
    const int lane = tid & 31;

    if (bid < 8) {
        const int gwarp = bid * 32 + wi;     // 0..255
        {
            float4 cc = __ldg((const float4*)cls_w + lane);
            float4 a  = __ldg((const float4*)(f_w + (size_t)gwarp * C) + lane);
            float part = warp_sum(a.x * cc.x + a.y * cc.y +
                                  a.z * cc.z + a.w * cc.w);
            if (lane == 0) {
                if (gwarp < C) g_vec_u[gwarp] = part;
                else           g_vec_v[gwarp - C] = part;
            }
        }
        __syncthreads();
        if (tid == 0) flag_bump(&g_c1);
        flag_wait(&g_c1, 8u);
        {
            float4 vv = *((const float4*)g_vec_v + lane);
            float4 a  = __ldg((const float4*)(g_w + (size_t)gwarp * C) + lane);
            float part = warp_sum(a.x * vv.x + a.y * vv.y +
                                  a.z * vv.z + a.w * vv.w);
            if (lane == 0) {
                if (gwarp < C) g_vec_p[gwarp]     = part;
                else           g_vec_q[gwarp - C] = part;
            }
        }
        __syncthreads();
        if (tid == 0) flag_bump(&g_c2);
    } else if (bid == 8) {
        flag_wait(&g_c1, 8u);
        if (wi == 0) {
            float r = 0.f, s = 0.f, c = 0.f;
            #pragma unroll
            for (int k = lane; k < C; k += 32) {
                float vk = g_vec_v[k];
                r += __ldg(&g_w[2 * C * C + k]) * vk;
                s += __ldg(&g_b[k]) * vk;
                c += __ldg(&f_b[k]) * __ldg(&cls_w[k]);
            }
            r = warp_sum(r); s = warp_sum(s); c = warp_sum(c);
            if (lane == 0) {
                g_scalar_r  = r;
                g_scalar_s  = s;
                g_scalar_c0 = c + __ldg(&cls_b[0]);
            }
        }
        __syncthreads();
        if (tid == 0) flag_bump(&g_c2);
    } else {
        const int gw   = (bid - SB) * (P_NTHR / 32) + wi;   // 0..4447
        const int base = gw * NPW;
        const int cnt  = (base < N) ? ((N - base < NPW) ? (N - base) : NPW) : 0;
        float4 xv[NPW];
        #pragma unroll
        for (int j = 0; j < NPW; j++)
            if (j < cnt)
                xv[j] = __ldg((const float4*)(x + (size_t)(base + j) * C) + lane);

        {   // zero acc replicas: 139*1024 = 142336 >= 98304
            int i = (bid - SB) * P_NTHR + tid;
            if (i < NREP * NODE_CAP) g_acc64[i] = 0ULL;
        }

        flag_wait(&g_c2, (unsigned)SB);

        if (cnt > 0) {
            float4 qv = *((const float4*)g_vec_q + lane);
            float4 uv = *((const float4*)g_vec_u + lane);
            float4 pv = *((const float4*)g_vec_p + lane);
            #pragma unroll
            for (int j = 0; j < NPW; j++) {
                if (j < cnt) {
                    float dq = xv[j].x * qv.x + xv[j].y * qv.y +
                               xv[j].z * qv.z + xv[j].w * qv.w;
                    float du = xv[j].x * uv.x + xv[j].y * uv.y +
                               xv[j].z * uv.z + xv[j].w * uv.w;
                    float dp = xv[j].x * pv.x + xv[j].y * pv.y +
                               xv[j].z * pv.z + xv[j].w * pv.w;
                    #pragma unroll
                    for (int o = 16; o > 0; o >>= 1) {
                        dq += __shfl_xor_sync(0xffffffffu, dq, o);
                        du += __shfl_xor_sync(0xffffffffu, du, o);
                        dp += __shfl_xor_sync(0xffffffffu, dp, o);
                    }
                    if (lane == 0) {
                        g_t[base + j]   = dq;
                        g_ddp[base + j] = make_float2(du, dp);
                    }
                }
            }
        }
    }

    cudaTriggerProgrammaticLaunchCompletion();

    __syncthreads();
    if (tid == 0) {
        __threadfence();
        unsigned old = atomicAdd(&g_doneP, 1u);
        if (old == (unsigned)P_NBLK - 1u) {
            g_c1 = 0u; g_c2 = 0u; g_doneP = 0u;
            __threadfence();
        }
    }
}

// ============================ K2: edges (PDL + SMEM-staged t) ===============
// 148 x 1024, smem = N*4. Each thread owns pairs {i, i+T, i+2T}. Prologue
// loads all pair data (overlaps K1); after sync, stage g_t into SMEM, then
// LDS gathers + one u64 red per edge.
__global__ void __launch_bounds__(E_NTHR, 1)
edge_kernel(const void*  __restrict__ eidx,
            const float* __restrict__ ea,
            long long E, int N)
{
    extern __shared__ __align__(16) float st[];
    const int tid = threadIdx.x;
    const int bid = blockIdx.x;
    const long long T     = (long long)E_NBLK * E_NTHR;
    const long long pairs = E >> 1;
    const long long i0    = (long long)bid * E_NTHR + tid;

    // per-warp dtype sniff: int64 nonneg < 2^31 shows zeros at odd int32 slots
    const int lane = tid & 31;
    int is64;
    {
        const int* p = (const int*)eidx;
        int ok = (p[2 * lane + 1] == 0) &&
                 (p[2 * (lane + 32) + 1] == 0) &&
                 (p[2 * (lane + 64) + 1] == 0);
        unsigned b = __ballot_sync(0xffffffffu, ok);
        is64 = (b == 0xffffffffu) ? 1 : 0;
    }

    // Prologue: load up to 3 assigned pairs (independent of K1).
    long long s[6], d[6];
    float2 e2[3];
    bool act[3];
    #pragma unroll
    for (int k = 0; k < 3; k++) {
        const long long i = i0 + (long long)k * T;
        act[k] = (i < pairs);
        if (act[k]) {
            e2[k] = __ldg((const float2*)ea + i);
            if (is64) {
                const longlong2* ps = (const longlong2*)eidx;
                const longlong2* pd = (const longlong2*)((const long long*)eidx + E);
                longlong2 a = ps[i];
                longlong2 c = pd[i];
                s[2*k] = a.x; s[2*k+1] = a.y;
                d[2*k] = c.x; d[2*k+1] = c.y;
            } else {
                const int2* ps = (const int2*)eidx;
                const int2* pd = (const int2*)((const int*)eidx + E);
                int2 a = ps[i];
                int2 c = pd[i];
                s[2*k] = a.x; s[2*k+1] = a.y;
                d[2*k] = c.x; d[2*k+1] = c.y;
            }
        }
    }

    cudaGridDependencySynchronize();   // g_t / g_scalar_r / zeroed acc visible

    // Stage t into SMEM (coalesced float4 + tail).
    {
        const int n4 = N >> 2;
        const float4* t4 = (const float4*)g_t;
        float4* s4 = (float4*)st;
        for (int i = tid; i < n4; i += E_NTHR) s4[i] = t4[i];
        for (int i = (n4 << 2) + tid; i < N; i += E_NTHR) st[i] = g_t[i];
    }
    __syncthreads();

    const float rs = g_scalar_r;
    unsigned long long* acc =
        g_acc64 + (size_t)(bid & (NREP - 1)) * NODE_CAP;

    #pragma unroll
    for (int k = 0; k < 3; k++) {
        if (act[k]) {
            float v0 = st[s[2*k]]   + e2[k].x * rs;
            float v1 = st[s[2*k+1]] + e2[k].y * rs;
            red_u64(&acc[d[2*k]],   enc_edge(v0));
            red_u64(&acc[d[2*k+1]], enc_edge(v1));
        }
    }
    if (i0 == 0 && (E & 1)) {
        if (is64) {
            const long long* p = (const long long*)eidx;
            float v = st[p[E - 1]] + ea[E - 1] * rs;
            red_u64(&acc[p[2 * E - 1]], enc_edge(v));
        } else {
            const int* p = (const int*)eidx;
            float v = st[p[E - 1]] + ea[E - 1] * rs;
            red_u64(&acc[p[2 * E - 1]], enc_edge(v));
        }
    }
    // Implicit PDL trigger at exit: out kernel must see ALL reds.
}

// ============================ K3: output (PDL) ==============================
__global__ void __launch_bounds__(O_NTHR, 8)
out_kernel(float* __restrict__ out, int N, int twopart)
{
    const int n = blockIdx.x * O_NTHR + threadIdx.x;

    float2 ddp = make_float2(0.f, 0.f);
    if (n < N) ddp = g_ddp[n];

    cudaGridDependencySynchronize();   // all edge reds complete

    if (n >= N) return;

    unsigned long long acc = g_acc64[n]
                           + g_acc64[NODE_CAP + n]
                           + g_acc64[2 * NODE_CAP + n]
                           + g_acc64[3 * NODE_CAP + n];
    unsigned cnt = (unsigned)(acc >> CNT_SHIFT);
    unsigned long long raw = acc & ((1ULL << CNT_SHIFT) - 1ULL);
    float score = ddp.x + g_scalar_c0;
    if (cnt > 0u) {
        // hi, lo and 4096*cnt are exact integers < 2^24 in fp32.
        float hi = (float)(long long)(raw >> 18);
        float lo = (float)(int)(raw & 0x3FFFFULL);
        float sum_v = (hi - (float)ENC_OFFSET * (float)cnt) + lo * ENC_INV;
        score += ddp.y + sum_v / (float)cnt + g_scalar_s;
    }
    float pr = 1.0f / (1.0f + __expf(-score));
    if (twopart) {
        out[n]     = (pr > 0.5f) ? 1.0f : 0.0f;
        out[N + n] = pr;
    } else {
        out[n] = pr;
    }
}

// ============================ host ==========================================
static void launch_pdl(const void* func, dim3 grid, dim3 block, void** args,
                       int smem) {
    cudaLaunchConfig_t cfg = {};
    cfg.gridDim  = grid;
    cfg.blockDim = block;
    cfg.dynamicSmemBytes = (size_t)smem;
    cfg.stream = 0;
    cudaLaunchAttribute attr[1];
    attr[0].id = cudaLaunchAttributeProgrammaticStreamSerialization;
    attr[0].val.programmaticStreamSerializationAllowed = 1;
    cfg.attrs = attr;
    cfg.numAttrs = 1;
    cudaLaunchKernelExC(&cfg, func, args);
}

extern "C" void kernel_launch(void* const* d_in, const int* in_sizes, int n_in,
                              void* d_out, int out_size) {
    // metadata order: x_a, edge_index, edge_attr, g_w, g_b, f_w, f_b, cls_w, cls_b
    const float* x_a        = (const float*)d_in[0];
    const void*  edge_index =               d_in[1];
    const float* edge_attr  = (const float*)d_in[2];
    const float* g_w        = (const float*)d_in[3];
    const float* g_b        = (const float*)d_in[4];
    const float* f_w        = (const float*)d_in[5];
    const float* f_b        = (const float*)d_in[6];
    const float* cls_w      = (const float*)d_in[7];
    const float* cls_b      = (const float*)d_in[8];
    float* out = (float*)d_out;

    int       N = in_sizes[0] / C;        // 20000
    long long E = (long long)in_sizes[2]; // 640000
    int twopart = (out_size >= 2 * N) ? 1 : 0;
    const int smem = N * (int)sizeof(float);   // 78.1 KB

    static int smem_set = 0;
    if (!smem_set) {
        cudaFuncSetAttribute(edge_kernel,
                             cudaFuncAttributeMaxDynamicSharedMemorySize,
                             smem);
        smem_set = 1;
    }

    pre_kernel<<<P_NBLK, P_NTHR>>>(x_a, g_w, g_b, f_w, f_b, cls_w, cls_b, N);

    {   // edge kernel: 148 x 1024, SMEM-staged t
        void* args[] = {(void*)&edge_index, (void*)&edge_attr,
                        (void*)&E, (void*)&N};
        launch_pdl((const void*)edge_kernel, dim3(E_NBLK), dim3(E_NTHR),
                   args, smem);
    }
    {   // out kernel
        dim3 grid((N + O_NTHR - 1) / O_NTHR);
        void* args[] = {(void*)&out, (void*)&N, (void*)&twopart};
        launch_pdl((const void*)out_kernel, grid, dim3(O_NTHR), args, 0);
    }
}

// round 16
// speedup vs baseline: 1.2183x; 1.0152x over previous
#include <cuda_runtime.h>
#include <cuda_bf16.h>

// ---------------------------------------------------------------------------
// CutsSelector collapsed to scalar-per-node form:
//   v = f2@cls ; u = f1@cls ; p = Wd@v ; q = Ws@v
//   r = we.v ; s = g_b.v ; c0 = f_b.cls + cls_b
//   t[n]=x[n].q ; du[n]=x[n].u ; dp[n]=x[n].p
//   per edge: acc64[rep][dst] += enc(t[src] + r*ea)  (ONE u64 L2 red, exact
//     fixed point: bits 0..51 value-sum, bits 52..63 count; 4 replicas)
//   score = du + c0 + (cnt>0 ? dp + sum_v/cnt + s : 0) ; probs = sigmoid
//
// THREE kernels, PDL-chained (best R15: 19.2us):
//   K1 pre_kernel (296 x 512, launch_bounds(512,2) => 64 warps/SM): flag-based
//      setup (blocks 0..16) || x prologue + dots (blocks 17..295).
//   K2 edge_kernel (148 x 1024, 78KB smem): prologue edge loads during K1;
//      stages g_t into SMEM; LDS gathers + one u64 red per edge (R15 win).
//   K3 out_kernel (PDL): decode + sigmoid.
// ---------------------------------------------------------------------------

#define C 128
#define NODE_CAP 24576
#define NREP 4
#define P_NBLK 296
#define P_NTHR 512
#define SB     17           /* setup blocks: 0..15 matvec, 16 scalars */
#define NPW    5            /* nodes/warp, blocks 17..295: 279*16*5 = 22320 >= N */
#define E_NBLK 148
#define E_NTHR 1024
#define O_NTHR 256

#define ENC_OFFSET 4096
#define ENC_SCALE  262144.0f          /* 2^18 */
#define ENC_INV    (1.0f / 262144.0f)
#define CNT_SHIFT  52

__device__ __align__(16) float  g_vec_u[C];
__device__ __align__(16) float  g_vec_v[C];
__device__ __align__(16) float  g_vec_p[C];
__device__ __align__(16) float  g_vec_q[C];
__device__ float  g_scalar_r;
__device__ float  g_scalar_s;
__device__ float  g_scalar_c0;
__device__ __align__(16) float  g_t[NODE_CAP];
__device__ __align__(16) float2 g_ddp[NODE_CAP];        // {du, dp}
__device__ __align__(16) unsigned long long g_acc64[NREP * NODE_CAP];
__device__ unsigned g_c1, g_c2, g_doneP;                // K1 flags (self-reset)

__device__ __forceinline__ float warp_sum(float v) {
    #pragma unroll
    for (int o = 16; o > 0; o >>= 1) v += __shfl_xor_sync(0xffffffffu, v, o);
    return v;
}

// Exact fixed-point edge encoding (validated R5-R15, rel_err 1.25e-7).
__device__ __forceinline__ unsigned long long enc_edge(float v) {
    int   vi  = __float2int_rn(v);
    float fr  = v - (float)vi;                   // exact, |fr| <= 0.5
    int   fri = __float2int_rn(fr * ENC_SCALE);  // exact product (2^18)
    return ((unsigned long long)(unsigned)(vi + ENC_OFFSET) << 18)
         + (unsigned long long)(long long)fri
         + (1ULL << CNT_SHIFT);
}

__device__ __forceinline__ void red_u64(unsigned long long* p,
                                        unsigned long long v) {
    asm volatile("red.global.add.u64 [%0], %1;" :: "l"(p), "l"(v) : "memory");
}

__device__ __forceinline__ void flag_bump(unsigned* c) {
    __threadfence();
    atomicAdd(c, 1u);
}

__device__ __forceinline__ void flag_wait(unsigned* c, unsigned target) {
    if (threadIdx.x == 0) {
        unsigned v;
        do {
            asm volatile("ld.global.acquire.gpu.u32 %0, [%1];"
                         : "=r"(v) : "l"(c));
        } while (v < target);
    }
    __syncthreads();
}

// ============================ K1: setup flags + t ===========================
__global__ void __launch_bounds__(P_NTHR, 2)
pre_kernel(const float* __restrict__ x,
           const float* __restrict__ g_w,   // [257,128]
           const float* __restrict__ g_b,   // [128]
           const float* __restrict__ f_w,   // [256,128]
           const float* __restrict__ f_b,   // [128]
           const float* __restrict__ cls_w, // [128]
           const float* __restrict__ cls_b, // [1]
           int N)
{
    const int tid  = threadIdx.x;
    const int bid  = blockIdx.x;
    const int wi   = tid >> 5;           // 0..15
    const int lane = tid & 31;

    if (bid < 16) {
        // ---- stage 1: one f_w row per warp (gwarp = bid*16+wi, 0..255) ----
        const int gwarp = bid * 16 + wi;
        {
            float4 cc = __ldg((const float4*)cls_w + lane);
            float4 a  = __ldg((const float4*)(f_w + (size_t)gwarp * C) + lane);
            float part = warp_sum(a.x * cc.x + a.y * cc.y +
                                  a.z * cc.z + a.w * cc.w);
            if (lane == 0) {
                if (gwarp < C) g_vec_u[gwarp] = part;
                else           g_vec_v[gwarp - C] = part;
            }
        }
        __syncthreads();
        if (tid == 0) flag_bump(&g_c1);
        flag_wait(&g_c1, 16u);

        // ---- stage 2: one g_w row per warp ----
        {
            float4 vv = *((const float4*)g_vec_v + lane);  // L2-hot
            float4 a  = __ldg((const float4*)(g_w + (size_t)gwarp * C) + lane);
            float part = warp_sum(a.x * vv.x + a.y * vv.y +
                                  a.z * vv.z + a.w * vv.w);
            if (lane == 0) {
                if (gwarp < C) g_vec_p[gwarp]     = part;
                else           g_vec_q[gwarp - C] = part;
            }
        }
        __syncthreads();
        if (tid == 0) flag_bump(&g_c2);
    } else if (bid == 16) {
        // ---- scalars: wait for v, then r/s/c0 ----
        flag_wait(&g_c1, 16u);
        if (wi == 0) {
            float r = 0.f, s = 0.f, c = 0.f;
            #pragma unroll
            for (int k = lane; k < C; k += 32) {
                float vk = g_vec_v[k];
                r += __ldg(&g_w[2 * C * C + k]) * vk;
                s += __ldg(&g_b[k]) * vk;
                c += __ldg(&f_b[k]) * __ldg(&cls_w[k]);
            }
            r = warp_sum(r); s = warp_sum(s); c = warp_sum(c);
            if (lane == 0) {
                g_scalar_r  = r;
                g_scalar_s  = s;
                g_scalar_c0 = c + __ldg(&cls_b[0]);
            }
        }
        __syncthreads();
        if (tid == 0) flag_bump(&g_c2);
    } else {
        // ---- data blocks 17..295: prologue x loads + zero acc ----
        const int gw   = (bid - SB) * (P_NTHR / 32) + wi;   // 0..4463
        const int base = gw * NPW;
        const int cnt  = (base < N) ? ((N - base < NPW) ? (N - base) : NPW) : 0;
        float4 xv[NPW];
        #pragma unroll
        for (int j = 0; j < NPW; j++)
            if (j < cnt)
                xv[j] = __ldg((const float4*)(x + (size_t)(base + j) * C) + lane);

        {   // zero acc replicas: 279*512 = 142848 >= 98304
            int i = (bid - SB) * P_NTHR + tid;
            if (i < NREP * NODE_CAP) g_acc64[i] = 0ULL;
        }

        // ---- wait only for setup completion ----
        flag_wait(&g_c2, (unsigned)SB);

        if (cnt > 0) {
            float4 qv = *((const float4*)g_vec_q + lane);
            float4 uv = *((const float4*)g_vec_u + lane);
            float4 pv = *((const float4*)g_vec_p + lane);
            #pragma unroll
            for (int j = 0; j < NPW; j++) {
                if (j < cnt) {
                    float dq = xv[j].x * qv.x + xv[j].y * qv.y +
                               xv[j].z * qv.z + xv[j].w * qv.w;
                    float du = xv[j].x * uv.x + xv[j].y * uv.y +
                               xv[j].z * uv.z + xv[j].w * uv.w;
                    float dp = xv[j].x * pv.x + xv[j].y * pv.y +
                               xv[j].z * pv.z + xv[j].w * pv.w;
                    #pragma unroll
                    for (int o = 16; o > 0; o >>= 1) {
                        dq += __shfl_xor_sync(0xffffffffu, dq, o);
                        du += __shfl_xor_sync(0xffffffffu, du, o);
                        dp += __shfl_xor_sync(0xffffffffu, dp, o);
                    }
                    if (lane == 0) {
                        g_t[base + j]   = dq;
                        g_ddp[base + j] = make_float2(du, dp);
                    }
                }
            }
        }
    }

    cudaTriggerProgrammaticLaunchCompletion();

    // ---- completion count; last block resets flags for graph replay ----
    __syncthreads();
    if (tid == 0) {
        __threadfence();
        unsigned old = atomicAdd(&g_doneP, 1u);
        if (old == (unsigned)P_NBLK - 1u) {
            g_c1 = 0u; g_c2 = 0u; g_doneP = 0u;
            __threadfence();
        }
    }
}

// ============================ K2: edges (PDL + SMEM-staged t, R15) ==========
__global__ void __launch_bounds__(E_NTHR, 1)
edge_kernel(const void*  __restrict__ eidx,
            const float* __restrict__ ea,
            long long E, int N)
{
    extern __shared__ __align__(16) float st[];
    const int tid = threadIdx.x;
    const int bid = blockIdx.x;
    const long long T     = (long long)E_NBLK * E_NTHR;
    const long long pairs = E >> 1;
    const long long i0    = (long long)bid * E_NTHR + tid;

    // per-warp dtype sniff: int64 nonneg < 2^31 shows zeros at odd int32 slots
    const int lane = tid & 31;
    int is64;
    {
        const int* p = (const int*)eidx;
        int ok = (p[2 * lane + 1] == 0) &&
                 (p[2 * (lane + 32) + 1] == 0) &&
                 (p[2 * (lane + 64) + 1] == 0);
        unsigned b = __ballot_sync(0xffffffffu, ok);
        is64 = (b == 0xffffffffu) ? 1 : 0;
    }

    // Prologue: load up to 3 assigned pairs (independent of K1).
    long long s[6], d[6];
    float2 e2[3];
    bool act[3];
    #pragma unroll
    for (int k = 0; k < 3; k++) {
        const long long i = i0 + (long long)k * T;
        act[k] = (i < pairs);
        if (act[k]) {
            e2[k] = __ldg((const float2*)ea + i);
            if (is64) {
                const longlong2* ps = (const longlong2*)eidx;
                const longlong2* pd = (const longlong2*)((const long long*)eidx + E);
                longlong2 a = ps[i];
                longlong2 c = pd[i];
                s[2*k] = a.x; s[2*k+1] = a.y;
                d[2*k] = c.x; d[2*k+1] = c.y;
            } else {
                const int2* ps = (const int2*)eidx;
                const int2* pd = (const int2*)((const int*)eidx + E);
                int2 a = ps[i];
                int2 c = pd[i];
                s[2*k] = a.x; s[2*k+1] = a.y;
                d[2*k] = c.x; d[2*k+1] = c.y;
            }
        }
    }

    cudaGridDependencySynchronize();   // g_t / g_scalar_r / zeroed acc visible

    // Stage t into SMEM (coalesced float4 + tail).
    {
        const int n4 = N >> 2;
        const float4* t4 = (const float4*)g_t;
        float4* s4 = (float4*)st;
        for (int i = tid; i < n4; i += E_NTHR) s4[i] = t4[i];
        for (int i = (n4 << 2) + tid; i < N; i += E_NTHR) st[i] = g_t[i];
    }
    __syncthreads();

    const float rs = g_scalar_r;
    unsigned long long* acc =
        g_acc64 + (size_t)(bid & (NREP - 1)) * NODE_CAP;

    #pragma unroll
    for (int k = 0; k < 3; k++) {
        if (act[k]) {
            float v0 = st[s[2*k]]   + e2[k].x * rs;
            float v1 = st[s[2*k+1]] + e2[k].y * rs;
            red_u64(&acc[d[2*k]],   enc_edge(v0));
            red_u64(&acc[d[2*k+1]], enc_edge(v1));
        }
    }
    if (i0 == 0 && (E & 1)) {
        if (is64) {
            const long long* p = (const long long*)eidx;
            float v = st[p[E - 1]] + ea[E - 1] * rs;
            red_u64(&acc[p[2 * E - 1]], enc_edge(v));
        } else {
            const int* p = (const int*)eidx;
            float v = st[p[E - 1]] + ea[E - 1] * rs;
            red_u64(&acc[p[2 * E - 1]], enc_edge(v));
        }
    }
    // Implicit PDL trigger at exit: out kernel must see ALL reds.
}

// ============================ K3: output (PDL) ==============================
__global__ void __launch_bounds__(O_NTHR, 8)
out_kernel(float* __restrict__ out, int N, int twopart)
{
    const int n = blockIdx.x * O_NTHR + threadIdx.x;

    float2 ddp = make_float2(0.f, 0.f);
    if (n < N) ddp = g_ddp[n];

    cudaGridDependencySynchronize();   // all edge reds complete

    if (n >= N) return;

    unsigned long long acc = g_acc64[n]
                           + g_acc64[NODE_CAP + n]
                           + g_acc64[2 * NODE_CAP + n]
                           + g_acc64[3 * NODE_CAP + n];
    unsigned cnt = (unsigned)(acc >> CNT_SHIFT);
    unsigned long long raw = acc & ((1ULL << CNT_SHIFT) - 1ULL);
    float score = ddp.x + g_scalar_c0;
    if (cnt > 0u) {
        // hi, lo and 4096*cnt are exact integers < 2^24 in fp32.
        float hi = (float)(long long)(raw >> 18);
        float lo = (float)(int)(raw & 0x3FFFFULL);
        float sum_v = (hi - (float)ENC_OFFSET * (float)cnt) + lo * ENC_INV;
        score += ddp.y + sum_v / (float)cnt + g_scalar_s;
    }
    float pr = 1.0f / (1.0f + __expf(-score));
    if (twopart) {
        out[n]     = (pr > 0.5f) ? 1.0f : 0.0f;
        out[N + n] = pr;
    } else {
        out[n] = pr;
    }
}

// ============================ host ==========================================
static void launch_pdl(const void* func, dim3 grid, dim3 block, void** args,
                       int smem) {
    cudaLaunchConfig_t cfg = {};
    cfg.gridDim  = grid;
    cfg.blockDim = block;
    cfg.dynamicSmemBytes = (size_t)smem;
    cfg.stream = 0;
    cudaLaunchAttribute attr[1];
    attr[0].id = cudaLaunchAttributeProgrammaticStreamSerialization;
    attr[0].val.programmaticStreamSerializationAllowed = 1;
    cfg.attrs = attr;
    cfg.numAttrs = 1;
    cudaLaunchKernelExC(&cfg, func, args);
}

extern "C" void kernel_launch(void* const* d_in, const int* in_sizes, int n_in,
                              void* d_out, int out_size) {
    // metadata order: x_a, edge_index, edge_attr, g_w, g_b, f_w, f_b, cls_w, cls_b
    const float* x_a        = (const float*)d_in[0];
    const void*  edge_index =               d_in[1];
    const float* edge_attr  = (const float*)d_in[2];
    const float* g_w        = (const float*)d_in[3];
    const float* g_b        = (const float*)d_in[4];
    const float* f_w        = (const float*)d_in[5];
    const float* f_b        = (const float*)d_in[6];
    const float* cls_w      = (const float*)d_in[7];
    const float* cls_b      = (const float*)d_in[8];
    float* out = (float*)d_out;

    int       N = in_sizes[0] / C;        // 20000
    long long E = (long long)in_sizes[2]; // 640000
    int twopart = (out_size >= 2 * N) ? 1 : 0;
    const int smem = N * (int)sizeof(float);   // 78.1 KB

    static int smem_set = 0;
    if (!smem_set) {
        cudaFuncSetAttribute(edge_kernel,
                             cudaFuncAttributeMaxDynamicSharedMemorySize,
                             smem);
        smem_set = 1;
    }

    pre_kernel<<<P_NBLK, P_NTHR>>>(x_a, g_w, g_b, f_w, f_b, cls_w, cls_b, N);

    {   // edge kernel: 148 x 1024, SMEM-staged t
        void* args[] = {(void*)&edge_index, (void*)&edge_attr,
                        (void*)&E, (void*)&N};
        launch_pdl((const void*)edge_kernel, dim3(E_NBLK), dim3(E_NTHR),
                   args, smem);
    }
    {   // out kernel
        dim3 grid((N + O_NTHR - 1) / O_NTHR);
        void* args[] = {(void*)&out, (void*)&N, (void*)&twopart};
        launch_pdl((const void*)out_kernel, grid, dim3(O_NTHR), args, 0);
    }
}